// round 15
// baseline (speedup 1.0000x reference)
#include <cuda_runtime.h>
#include <cuda_bf16.h>

// Problem: B=16, C=64, H=128, W=128
//   masked_l1[b,c] = sum_hw |pre-gt| * mask ; nonzero[b,c] = count(mask!=0)
//   loss = sum_bc( masked_l1 / max(nonzero,1) ) / B
//
// R15: continue the R14 direction (ramp-in chain trims gave 35.3->33.2us,
// DRAM 73->76%). Two further trims, config otherwise identical
// (4096 CTAs x 512 thr, SEGS=4, 6 front-batched LDG.128, __ldcs,
// single fence + global ticket, in-kernel finalize):
//  1. base index = seg * SEG_V4 (segments are globally contiguous; the
//     bc/part split is only needed for the atomic target) — removes two
//     dependent IMADs before the first LDG.
//  2. byte-offset addressing hoisted once (<<4), tensors indexed via
//     char* + shared byte offset; 2nd load per tensor is [R+8192] imm.

#define BATCH   16
#define CHAN    64
#define HW      (128 * 128)            // 16384 elems per (b,c)
#define NBC     (BATCH * CHAN)         // 1024
#define SEGS    4
#define NSEG    (NBC * SEGS)           // 4096 CTAs
#define SEG_V4  (HW / 4 / SEGS)        // 1024 float4 per segment
#define THREADS 512
#define NWARP   (THREADS / 32)         // 16
#define V4_PER_THREAD (SEG_V4 / THREADS)  // 2

__device__ float    g_s[NBC];
__device__ float    g_cnt[NBC];
__device__ unsigned g_ctr;

__global__ __launch_bounds__(THREADS, 4)   // 2048 thr/SM, 32 regs/thread
void l1loss_kernel(const float4* __restrict__ pre,
                   const float4* __restrict__ gt,
                   const float4* __restrict__ mask,
                   float* __restrict__ out) {
    const int seg = blockIdx.x;                       // 0..4095
    // Segments are globally contiguous: base = seg * SEG_V4 + tid.
    // (bc decomposition only needed later for the atomic target.)
    const unsigned byte0 = ((unsigned)seg * SEG_V4 + threadIdx.x) << 4;

    const char* pre_b  = (const char*)pre  + byte0;
    const char* gt_b   = (const char*)gt   + byte0;
    const char* mask_b = (const char*)mask + byte0;

    // Front-batch all 6 LDG.128 (stride THREADS*16 = 8192B -> imm offset).
    float4 p[V4_PER_THREAD], g[V4_PER_THREAD], m[V4_PER_THREAD];
    #pragma unroll
    for (int i = 0; i < V4_PER_THREAD; i++)
        p[i] = __ldcs((const float4*)(pre_b  + i * (THREADS * 16)));
    #pragma unroll
    for (int i = 0; i < V4_PER_THREAD; i++)
        g[i] = __ldcs((const float4*)(gt_b   + i * (THREADS * 16)));
    #pragma unroll
    for (int i = 0; i < V4_PER_THREAD; i++)
        m[i] = __ldcs((const float4*)(mask_b + i * (THREADS * 16)));

    float s   = 0.0f;
    float cnt = 0.0f;
    #pragma unroll
    for (int i = 0; i < V4_PER_THREAD; i++) {
        s += fabsf(p[i].x - g[i].x) * m[i].x;
        s += fabsf(p[i].y - g[i].y) * m[i].y;
        s += fabsf(p[i].z - g[i].z) * m[i].z;
        s += fabsf(p[i].w - g[i].w) * m[i].w;
        cnt += m[i].x + m[i].y;     // mask is exactly {0,1}: sum == count
        cnt += m[i].z + m[i].w;
    }

    // Warp reduce
    #pragma unroll
    for (int off = 16; off > 0; off >>= 1) {
        s   += __shfl_down_sync(0xFFFFFFFFu, s,   off);
        cnt += __shfl_down_sync(0xFFFFFFFFu, cnt, off);
    }

    __shared__ float sh_s[NWARP];
    __shared__ float sh_c[NWARP];
    __shared__ int   sh_last;
    const int lane = threadIdx.x & 31;
    const int wid  = threadIdx.x >> 5;
    if (lane == 0) { sh_s[wid] = s; sh_c[wid] = cnt; }
    __syncthreads();

    if (threadIdx.x < 32) {
        s   = (lane < NWARP) ? sh_s[lane] : 0.0f;
        cnt = (lane < NWARP) ? sh_c[lane] : 0.0f;
        #pragma unroll
        for (int off = 8; off > 0; off >>= 1) {   // reduce 16 lanes
            s   += __shfl_down_sync(0xFFFFFFFFu, s,   off);
            cnt += __shfl_down_sync(0xFFFFFFFFu, cnt, off);
        }
        if (lane == 0) {
            const int bc = seg >> 2;              // atomic target only
            atomicAdd(&g_s[bc],   s);
            atomicAdd(&g_cnt[bc], cnt);
            __threadfence();
            const unsigned old = atomicAdd(&g_ctr, 1u);
            sh_last = (old == (unsigned)(NSEG - 1)) ? 1 : 0;
        }
    }
    __syncthreads();

    // Last CTA finalizes: divide per-bc, sum, write scalar, reset scratch.
    if (sh_last) {
        float ss[NBC / THREADS], cc[NBC / THREADS];
        #pragma unroll
        for (int j = 0; j < NBC / THREADS; j++) {
            const int i = threadIdx.x + j * THREADS;
            ss[j] = __ldcg(&g_s[i]);
            cc[j] = __ldcg(&g_cnt[i]);
        }
        float q = 0.0f;
        #pragma unroll
        for (int j = 0; j < NBC / THREADS; j++) {
            const int i = threadIdx.x + j * THREADS;
            q += ss[j] / fmaxf(cc[j], 1.0f);
            g_s[i]   = 0.0f;                      // reset for next replay
            g_cnt[i] = 0.0f;
        }
        #pragma unroll
        for (int off = 16; off > 0; off >>= 1)
            q += __shfl_down_sync(0xFFFFFFFFu, q, off);

        if (lane == 0) sh_s[wid] = q;
        __syncthreads();
        if (threadIdx.x < 32) {
            q = (lane < NWARP) ? sh_s[lane] : 0.0f;
            #pragma unroll
            for (int off = 8; off > 0; off >>= 1)
                q += __shfl_down_sync(0xFFFFFFFFu, q, off);
            if (lane == 0) {
                out[0] = q * (1.0f / (float)BATCH);
                g_ctr  = 0;                       // reset ticket for next replay
            }
        }
    }
}

extern "C" void kernel_launch(void* const* d_in, const int* in_sizes, int n_in,
                              void* d_out, int out_size) {
    const float4* pre  = (const float4*)d_in[0];
    const float4* gt   = (const float4*)d_in[1];
    const float4* mask = (const float4*)d_in[2];
    float* out = (float*)d_out;

    l1loss_kernel<<<NSEG, THREADS>>>(pre, gt, mask, out);
}